// round 9
// baseline (speedup 1.0000x reference)
#include <cuda_runtime.h>
#include <cstdint>

// ---------------- problem constants ----------------
#define BB      64
#define HH      56
#define WWID    56
#define CC      256
#define WSZ     7
#define SHIFTV  3
#define NHEADS  8
#define NTOK    49
#define NROWS   (BB*HH*WWID)     // 200704
#define NWIN    (BB*64)          // 4096 windows
#define NBIAS   (64*NHEADS*NTOK*NTOK)

// ---------------- scratch (device globals; no allocation allowed) ----------------
__device__ float g_qkv[(size_t)NROWS * 768];
__device__ float g_o  [(size_t)NROWS * 256];
__device__ float g_x2 [(size_t)NROWS * 256];
__device__ float g_h1 [(size_t)NROWS * 1024];
__device__ float g_bias[NBIAS];
__device__ float g_mean1[NROWS], g_rstd1[NROWS];
__device__ float g_mean2[NROWS], g_rstd2[NROWS];
__device__ float g_wqf [768 * 256];
__device__ float g_bqf [768];
__device__ float g_wf1f[1024 * 256];
__device__ float g_bf1f[1024];

// ---------------- helpers ----------------
// window-order row r -> natural-order row (shift + window-partition bijection)
__device__ __forceinline__ int src_row(int r) {
    int win = r / NTOK;
    int t   = r - win * NTOK;
    int b    = win >> 6;
    int wIdx = win & 63;
    int i = t / WSZ;
    int j = t - i * WSZ;
    int hs = (wIdx >> 3) * WSZ + i;
    int ws = (wIdx & 7)  * WSZ + j;
    int h0 = hs + SHIFTV; if (h0 >= HH)   h0 -= HH;
    int w0 = ws + SHIFTV; if (w0 >= WWID) w0 -= WWID;
    return (b * HH + h0) * WWID + w0;
}

__device__ __forceinline__ unsigned tf32r(float f) {
    unsigned u;
    asm("cvt.rna.tf32.f32 %0, %1;" : "=r"(u) : "f"(f));
    return u;
}
__device__ __forceinline__ float4 tf4(float4 v) {
    return make_float4(__uint_as_float(tf32r(v.x)), __uint_as_float(tf32r(v.y)),
                       __uint_as_float(tf32r(v.z)), __uint_as_float(tf32r(v.w)));
}
__device__ __forceinline__ float4 lntf4(float4 v, float m, float r) {
    return make_float4(__uint_as_float(tf32r((v.x - m) * r)),
                       __uint_as_float(tf32r((v.y - m) * r)),
                       __uint_as_float(tf32r((v.z - m) * r)),
                       __uint_as_float(tf32r((v.w - m) * r)));
}
__device__ __forceinline__ void mma8(float* c, const unsigned* a, const unsigned* b) {
    asm volatile(
        "mma.sync.aligned.m16n8k8.row.col.f32.tf32.tf32.f32 "
        "{%0,%1,%2,%3},{%4,%5,%6,%7},{%8,%9},{%0,%1,%2,%3};\n"
        : "+f"(c[0]), "+f"(c[1]), "+f"(c[2]), "+f"(c[3])
        : "r"(a[0]), "r"(a[1]), "r"(a[2]), "r"(a[3]), "r"(b[0]), "r"(b[1]));
}
__device__ __forceinline__ float fgelu(float v) {
    return v / (1.f + __expf(-1.702f * v));
}

// ---------------- fold LN affine into weights: W' = W*g ; b' = b + W @ beta ----------------
__global__ __launch_bounds__(256)
void fold_kernel(const float* __restrict__ qkv_w, const float* __restrict__ qkv_b,
                 const float* __restrict__ g1,    const float* __restrict__ b1,
                 const float* __restrict__ fc1_w, const float* __restrict__ fc1_b,
                 const float* __restrict__ g2,    const float* __restrict__ b2)
{
    __shared__ float red[256];
    int r = blockIdx.x;
    int t = threadIdx.x;
    const float *W, *bias, *gg, *bv; float *wout, *bout; int row;
    if (r < 768) { W = qkv_w; bias = qkv_b; gg = g1; bv = b1; wout = g_wqf;  bout = g_bqf;  row = r; }
    else         { W = fc1_w; bias = fc1_b; gg = g2; bv = b2; wout = g_wf1f; bout = g_bf1f; row = r - 768; }
    float w = W[row * 256 + t];
    wout[row * 256 + t] = w * gg[t];
    red[t] = w * bv[t];
    __syncthreads();
    for (int s = 128; s > 0; s >>= 1) { if (t < s) red[t] += red[t + s]; __syncthreads(); }
    if (t == 0) bout[row] = bias[row] + red[0];
}

// ---------------- per-row LN stats (warp per row) ----------------
template<int WHICH>
__global__ __launch_bounds__(256)
void row_stats(const float* __restrict__ Xin)
{
    const float* X = WHICH ? (const float*)g_x2 : Xin;
    int row  = blockIdx.x * 8 + (threadIdx.x >> 5);
    int lane = threadIdx.x & 31;
    const float4* p = (const float4*)(X + (size_t)row * 256);
    float4 u = p[lane];
    float4 w = p[lane + 32];
    float s = u.x + u.y + u.z + u.w + w.x + w.y + w.z + w.w;
    float q = u.x*u.x + u.y*u.y + u.z*u.z + u.w*u.w
            + w.x*w.x + w.y*w.y + w.z*w.z + w.w*w.w;
    #pragma unroll
    for (int o = 16; o > 0; o >>= 1) {
        s += __shfl_xor_sync(0xffffffffu, s, o);
        q += __shfl_xor_sync(0xffffffffu, q, o);
    }
    if (lane == 0) {
        float m   = s * (1.f / 256.f);
        float var = q * (1.f / 256.f) - m * m;
        if (WHICH) { g_mean2[row] = m; g_rstd2[row] = rsqrtf(var + 1e-5f); }
        else       { g_mean1[row] = m; g_rstd1[row] = rsqrtf(var + 1e-5f); }
    }
}

// ---------------- combined attention bias: mask + rpb ----------------
__global__ __launch_bounds__(256)
void bias_kernel(const float* __restrict__ mask, const float* __restrict__ rpb,
                 const int* __restrict__ relidx)
{
    int wh = blockIdx.x;              // 0..511  (wIdx*8 + head)
    int w = wh >> 3, h = wh & 7;
    for (int e = threadIdx.x; e < NTOK * NTOK; e += 256)
        g_bias[(size_t)wh * (NTOK * NTOK) + e] = mask[(size_t)w * (NTOK * NTOK) + e]
                                               + rpb[relidx[e] * NHEADS + h];
}

// ---------------- tf32 GEMM: 128x128x16 tile, 8 warps, double-buffered ----------------
constexpr int E_QKV = 0, E_PROJ = 1, E_FC1 = 2, E_FC2 = 3;

template<int EPI, int NTOT, int KTOT>
__global__ __launch_bounds__(256)
void gemm_tf32(const float* __restrict__ x,      // input x (A for QKV, shortcut for PROJ)
               const float* __restrict__ Warg,   // proj_w / fc2_w
               const float* __restrict__ barg,   // proj_b / fc2_b
               float* __restrict__ dout)         // only used by FC2
{
    const float* Ag;
    const float* Wg;
    const float* bcol;
    if (EPI == E_QKV)       { Ag = x;    Wg = g_wqf;  bcol = g_bqf;  }
    else if (EPI == E_PROJ) { Ag = g_o;  Wg = Warg;   bcol = barg;   }
    else if (EPI == E_FC1)  { Ag = g_x2; Wg = g_wf1f; bcol = g_bf1f; }
    else                    { Ag = g_h1; Wg = Warg;   bcol = barg;   }

    const int bn = blockIdx.x * 128;
    const int bm = blockIdx.y * 128;
    const int tid  = threadIdx.x;
    const int lrow = tid >> 1;
    const int lk   = (tid & 1) << 3;

    __shared__ float As[2][128 * 20];
    __shared__ float Bs[2][128 * 20];

    int arow = bm + lrow;
    const float* aptr;
    float lm = 0.f, lr = 1.f;
    bool do_ln = false;
    if (EPI == E_QKV) {
        int s = src_row(arow);
        aptr = Ag + (size_t)s * KTOT;
        lm = g_mean1[s]; lr = g_rstd1[s];
        do_ln = true;
    } else if (EPI == E_FC1) {
        aptr = Ag + (size_t)arow * KTOT;
        lm = g_mean2[arow]; lr = g_rstd2[arow];
        do_ln = true;
    } else {
        aptr = Ag + (size_t)arow * KTOT;
    }
    const float* bptr = Wg + (size_t)(bn + lrow) * KTOT;

    // prologue: stage tile 0
    float4 a0 = *(const float4*)(aptr + lk);
    float4 a1 = *(const float4*)(aptr + lk + 4);
    float4 b0 = *(const float4*)(bptr + lk);
    float4 b1 = *(const float4*)(bptr + lk + 4);
    {
        float4* as  = (float4*)&As[0][lrow * 20 + lk];
        float4* bsp = (float4*)&Bs[0][lrow * 20 + lk];
        if (do_ln) { as[0] = lntf4(a0, lm, lr); as[1] = lntf4(a1, lm, lr); }
        else       { as[0] = tf4(a0);           as[1] = tf4(a1);           }
        bsp[0] = tf4(b0); bsp[1] = tf4(b1);
    }
    __syncthreads();

    const int warp = tid >> 5, lane = tid & 31;
    const int wm = (warp & 3) << 5;     // 4 warps over M
    const int wn = (warp >> 2) << 6;    // 2 warps over N
    const int g  = lane >> 2, tg = lane & 3;

    float acc[2][8][4];
    #pragma unroll
    for (int mi = 0; mi < 2; ++mi)
        #pragma unroll
        for (int ni = 0; ni < 8; ++ni)
            #pragma unroll
            for (int l = 0; l < 4; ++l) acc[mi][ni][l] = 0.f;

    const int KT = KTOT / 16;
    for (int kt = 0; kt < KT; ++kt) {
        const float* Ac = As[kt & 1];
        const float* Bc = Bs[kt & 1];
        if (kt + 1 < KT) {
            int ko = (kt + 1) * 16 + lk;
            a0 = *(const float4*)(aptr + ko);
            a1 = *(const float4*)(aptr + ko + 4);
            b0 = *(const float4*)(bptr + ko);
            b1 = *(const float4*)(bptr + ko + 4);
        }
        #pragma unroll
        for (int kk = 0; kk < 16; kk += 8) {
            unsigned af[2][4], bf[8][2];
            #pragma unroll
            for (int mi = 0; mi < 2; ++mi) {
                int r0 = (wm + mi * 16 + g) * 20 + kk + tg;
                af[mi][0] = __float_as_uint(Ac[r0]);
                af[mi][1] = __float_as_uint(Ac[r0 + 8 * 20]);
                af[mi][2] = __float_as_uint(Ac[r0 + 4]);
                af[mi][3] = __float_as_uint(Ac[r0 + 8 * 20 + 4]);
            }
            #pragma unroll
            for (int ni = 0; ni < 8; ++ni) {
                int c0 = (wn + ni * 8 + g) * 20 + kk + tg;
                bf[ni][0] = __float_as_uint(Bc[c0]);
                bf[ni][1] = __float_as_uint(Bc[c0 + 4]);
            }
            #pragma unroll
            for (int mi = 0; mi < 2; ++mi)
                #pragma unroll
                for (int ni = 0; ni < 8; ++ni)
                    mma8(acc[mi][ni], af[mi], bf[ni]);
        }
        if (kt + 1 < KT) {
            int nxt = (kt + 1) & 1;
            float4* as  = (float4*)&As[nxt][lrow * 20 + lk];
            float4* bsp = (float4*)&Bs[nxt][lrow * 20 + lk];
            if (do_ln) { as[0] = lntf4(a0, lm, lr); as[1] = lntf4(a1, lm, lr); }
            else       { as[0] = tf4(a0);           as[1] = tf4(a1);           }
            bsp[0] = tf4(b0); bsp[1] = tf4(b1);
            __syncthreads();
        }
    }

    // epilogue
    #pragma unroll
    for (int mi = 0; mi < 2; ++mi) {
        int r0 = bm + wm + mi * 16 + g;
        int r1 = r0 + 8;
        int s0 = 0, s1 = 0;
        if (EPI == E_PROJ) { s0 = src_row(r0); s1 = src_row(r1); }
        #pragma unroll
        for (int ni = 0; ni < 8; ++ni) {
            int col = bn + wn + ni * 8 + (tg << 1);
            float bc0 = bcol[col], bc1 = bcol[col + 1];
            float v00 = acc[mi][ni][0] + bc0;
            float v01 = acc[mi][ni][1] + bc1;
            float v10 = acc[mi][ni][2] + bc0;
            float v11 = acc[mi][ni][3] + bc1;
            if (EPI == E_QKV) {
                *(float2*)&g_qkv[(size_t)r0 * NTOT + col] = make_float2(v00, v01);
                *(float2*)&g_qkv[(size_t)r1 * NTOT + col] = make_float2(v10, v11);
            } else if (EPI == E_PROJ) {
                float2 x0 = *(const float2*)&x[(size_t)s0 * NTOT + col];
                float2 x1 = *(const float2*)&x[(size_t)s1 * NTOT + col];
                *(float2*)&g_x2[(size_t)s0 * NTOT + col] = make_float2(x0.x + v00, x0.y + v01);
                *(float2*)&g_x2[(size_t)s1 * NTOT + col] = make_float2(x1.x + v10, x1.y + v11);
            } else if (EPI == E_FC1) {
                *(float2*)&g_h1[(size_t)r0 * NTOT + col] = make_float2(fgelu(v00), fgelu(v01));
                *(float2*)&g_h1[(size_t)r1 * NTOT + col] = make_float2(fgelu(v10), fgelu(v11));
            } else { // E_FC2: final residual
                float2 x0 = *(const float2*)&g_x2[(size_t)r0 * NTOT + col];
                float2 x1 = *(const float2*)&g_x2[(size_t)r1 * NTOT + col];
                *(float2*)&dout[(size_t)r0 * NTOT + col] = make_float2(x0.x + v00, x0.y + v01);
                *(float2*)&dout[(size_t)r1 * NTOT + col] = make_float2(x1.x + v10, x1.y + v11);
            }
        }
    }
}

// ---------------- windowed attention: one CTA per window, 8 heads looped ----------------
__global__ __launch_bounds__(256)
void attn_kernel()
{
    const int win  = blockIdx.x;           // 0..4095
    const int wIdx = win & 63;
    const int tid  = threadIdx.x;
    __shared__ float qs[NTOK][33], ks[NTOK][33], vs[NTOK][33];
    __shared__ float S[NTOK][52];
    const float scale = 0.17677669529663687f;   // 1/sqrt(32)
    const float* base = g_qkv + (size_t)win * NTOK * 768;

    // QK thread tiling: 16x16 threads, 4x4 register block covers 64x64 >= 49x49
    const int tn = tid >> 4, tm = tid & 15;
    int nI[4], mI[4]; bool nV[4], mV[4];
    #pragma unroll
    for (int i = 0; i < 4; ++i) {
        int n = tn + 16 * i; nV[i] = (n < NTOK); nI[i] = nV[i] ? n : 0;
        int m = tm + 16 * i; mV[i] = (m < NTOK); mI[i] = mV[i] ? m : 0;
    }
    const int lane = tid & 31;
    const int warp = tid >> 5;
    const int dpv  = tid & 31;     // headdim lane for PV
    const int npv  = tid >> 5;     // row group for PV

    for (int h = 0; h < NHEADS; ++h) {
        const int hoff = h * 32;
        // load q(prescaled)/k/v into smem
        for (int idx = tid; idx < NTOK * 32; idx += 256) {
            int t = idx >> 5, d = idx & 31;
            const float* rp = base + (size_t)t * 768 + hoff + d;
            qs[t][d] = rp[0] * scale;
            ks[t][d] = rp[256];
            vs[t][d] = rp[512];
        }
        __syncthreads();

        // S = q@k^T + bias
        float acc[4][4];
        #pragma unroll
        for (int i = 0; i < 4; ++i)
            #pragma unroll
            for (int j = 0; j < 4; ++j) acc[i][j] = 0.f;
        #pragma unroll 8
        for (int d = 0; d < 32; ++d) {
            float qv[4], kv[4];
            #pragma unroll
            for (int i = 0; i < 4; ++i) qv[i] = qs[nI[i]][d];
            #pragma unroll
            for (int j = 0; j < 4; ++j) kv[j] = ks[mI[j]][d];
            #pragma unroll
            for (int i = 0; i < 4; ++i)
                #pragma unroll
                for (int j = 0; j < 4; ++j) acc[i][j] += qv[i] * kv[j];
        }
        const float* bp = g_bias + (size_t)(wIdx * NHEADS + h) * (NTOK * NTOK);
        #pragma unroll
        for (int i = 0; i < 4; ++i)
            #pragma unroll
            for (int j = 0; j < 4; ++j)
                if (nV[i] && mV[j])
                    S[nI[i]][mI[j]] = acc[i][j] + bp[nI[i] * NTOK + mI[j]];
        __syncthreads();

        // softmax: warp per row
        for (int r = warp; r < NTOK; r += 8) {
            float v0 = S[r][lane];
            float v1 = (lane + 32 < NTOK) ? S[r][lane + 32] : -1e30f;
            float mx = fmaxf(v0, v1);
            #pragma unroll
            for (int o = 16; o > 0; o >>= 1) mx = fmaxf(mx, __shfl_xor_sync(0xffffffffu, mx, o));
            float e0 = __expf(v0 - mx);
            float e1 = (lane + 32 < NTOK) ? __expf(v1 - mx) : 0.f;
            float sm = e0 + e1;
            #pragma unroll
            for (int o = 16; o > 0; o >>= 1) sm += __shfl_xor_sync(0xffffffffu, sm, o);
            float inv = 1.f / sm;
            S[r][lane] = e0 * inv;
            if (lane + 32 < NTOK) S[r][lane + 32] = e1 * inv;
        }
        __syncthreads();

        // O = S @ V  (warp per row group; lane = head dim)
        for (int n = npv; n < NTOK; n += 8) {
            float o = 0.f;
            #pragma unroll 7
            for (int m = 0; m < NTOK; ++m) o += S[n][m] * vs[m][dpv];
            g_o[(size_t)(win * NTOK + n) * 256 + hoff + dpv] = o;
        }
        __syncthreads();
    }
}

// ---------------- launch ----------------
extern "C" void kernel_launch(void* const* d_in, const int* in_sizes, int n_in,
                              void* d_out, int out_size)
{
    const float* x       = (const float*)d_in[0];
    const float* norm1_g = (const float*)d_in[1];
    const float* norm1_b = (const float*)d_in[2];
    const float* qkv_w   = (const float*)d_in[3];
    const float* qkv_b   = (const float*)d_in[4];
    const float* rpb     = (const float*)d_in[5];
    const float* proj_w  = (const float*)d_in[6];
    const float* proj_b  = (const float*)d_in[7];
    const float* norm2_g = (const float*)d_in[8];
    const float* norm2_b = (const float*)d_in[9];
    const float* fc1_w   = (const float*)d_in[10];
    const float* fc1_b   = (const float*)d_in[11];
    const float* fc2_w   = (const float*)d_in[12];
    const float* fc2_b   = (const float*)d_in[13];
    const int*   relidx  = (const int*)d_in[14];
    const float* mask    = (const float*)d_in[15];
    float* out = (float*)d_out;
    (void)in_sizes; (void)n_in; (void)out_size;

    fold_kernel<<<1792, 256>>>(qkv_w, qkv_b, norm1_g, norm1_b,
                               fc1_w, fc1_b, norm2_g, norm2_b);
    row_stats<0><<<NROWS / 8, 256>>>(x);
    bias_kernel<<<512, 256>>>(mask, rpb, relidx);

    gemm_tf32<E_QKV, 768, 256><<<dim3(6, NROWS / 128), 256>>>(x, nullptr, nullptr, nullptr);
    attn_kernel<<<NWIN, 256>>>();
    gemm_tf32<E_PROJ, 256, 256><<<dim3(2, NROWS / 128), 256>>>(x, proj_w, proj_b, nullptr);
    row_stats<1><<<NROWS / 8, 256>>>(x);
    gemm_tf32<E_FC1, 1024, 256><<<dim3(8, NROWS / 128), 256>>>(nullptr, nullptr, nullptr, nullptr);
    gemm_tf32<E_FC2, 256, 1024><<<dim3(2, NROWS / 128), 256>>>(nullptr, fc2_w, fc2_b, out);
}

// round 13
// speedup vs baseline: 1.4611x; 1.4611x over previous
#include <cuda_runtime.h>
#include <cuda_fp16.h>
#include <cstdint>

// ---------------- problem constants ----------------
#define BB      64
#define HH      56
#define WWID    56
#define WSZ     7
#define SHIFTV  3
#define NHEADS  8
#define NTOK    49
#define NROWS   (BB*HH*WWID)     // 200704
#define NWIN    (BB*64)          // 4096 windows
#define NBIAS   (64*NHEADS*NTOK*NTOK)

// ---------------- scratch (device globals) ----------------
__device__ __half g_xn  [(size_t)NROWS * 256];   // LN1(x), window-order
__device__ __half g_qkvh[(size_t)NROWS * 768];   // qkv (window order)
__device__ __half g_oh  [(size_t)NROWS * 256];   // attention out (window order)
__device__ float  g_x2  [(size_t)NROWS * 256];   // post-attn residual (natural, f32)
__device__ __half g_x2n [(size_t)NROWS * 256];   // LN2(x2) (natural)
__device__ __half g_h1h [(size_t)NROWS * 1024];  // gelu(fc1)
__device__ float  g_bias[NBIAS];
__device__ __half g_wqh [768 * 256];
__device__ __half g_wph [256 * 256];
__device__ __half g_wf1h[1024 * 256];
__device__ __half g_wf2h[256 * 1024];

// ---------------- helpers ----------------
// window-order row r -> natural row (for PROJ scatter)
__device__ __forceinline__ int src_row(int r) {
    int win = r / NTOK;
    int t   = r - win * NTOK;
    int b    = win >> 6;
    int wIdx = win & 63;
    int i = t / WSZ;
    int j = t - i * WSZ;
    int hs = (wIdx >> 3) * WSZ + i;
    int ws = (wIdx & 7)  * WSZ + j;
    int h0 = hs + SHIFTV; if (h0 >= HH)   h0 -= HH;
    int w0 = ws + SHIFTV; if (w0 >= WWID) w0 -= WWID;
    return (b * HH + h0) * WWID + w0;
}
// natural row -> window-order row (for LN1 permuted write)
__device__ __forceinline__ int dst_row(int n) {
    int b   = n / (HH * WWID);
    int rem = n - b * (HH * WWID);
    int h0  = rem / WWID;
    int w0  = rem - h0 * WWID;
    int hs = h0 - SHIFTV; if (hs < 0) hs += HH;
    int ws = w0 - SHIFTV; if (ws < 0) ws += WWID;
    int win = b * 64 + (hs / WSZ) * 8 + (ws / WSZ);
    int tok = (hs % WSZ) * WSZ + (ws % WSZ);
    return win * NTOK + tok;
}
__device__ __forceinline__ float fgelu(float v) {
    return v / (1.f + __expf(-1.702f * v));
}
__device__ __forceinline__ uint32_t smem_u32(const void* p) {
    uint32_t a;
    asm("{ .reg .u64 t; cvta.to.shared.u64 t, %1; cvt.u32.u64 %0, t; }" : "=r"(a) : "l"(p));
    return a;
}
__device__ __forceinline__ void cp16(uint32_t dst, const void* src) {
    asm volatile("cp.async.cg.shared.global [%0], [%1], 16;" :: "r"(dst), "l"(src));
}
__device__ __forceinline__ void cp_commit() {
    asm volatile("cp.async.commit_group;");
}
__device__ __forceinline__ void cp_wait3() {
    asm volatile("cp.async.wait_group 3;");
}
__device__ __forceinline__ void hmma16(float* c, const uint32_t* a, const uint32_t* b) {
    asm volatile(
        "mma.sync.aligned.m16n8k16.row.col.f32.f16.f16.f32 "
        "{%0,%1,%2,%3},{%4,%5,%6,%7},{%8,%9},{%0,%1,%2,%3};\n"
        : "+f"(c[0]), "+f"(c[1]), "+f"(c[2]), "+f"(c[3])
        : "r"(a[0]), "r"(a[1]), "r"(a[2]), "r"(a[3]), "r"(b[0]), "r"(b[1]));
}

// ---------------- weight fp16 conversion ----------------
__global__ __launch_bounds__(256)
void w2h(const float* __restrict__ qw, const float* __restrict__ pw,
         const float* __restrict__ f1, const float* __restrict__ f2)
{
    int i = blockIdx.x * 256 + threadIdx.x;      // 0 .. 786431
    if (i < 196608) g_wqh[i] = __float2half(qw[i]);
    if (i < 65536)  g_wph[i] = __float2half(pw[i]);
    if (i < 262144) { g_wf1h[i] = __float2half(f1[i]); g_wf2h[i] = __float2half(f2[i]); }
}

// ---------------- LN kernels: stats + normalize + (optional permute), half out ----------------
template<int WHICH>   // 0: LN1 from x -> g_xn (permuted);  1: LN2 from g_x2 -> g_x2n
__global__ __launch_bounds__(256)
void ln_kernel(const float* __restrict__ Xin,
               const float* __restrict__ gam, const float* __restrict__ bet)
{
    const float* X = WHICH ? (const float*)g_x2 : Xin;
    int row  = blockIdx.x * 8 + (threadIdx.x >> 5);
    int lane = threadIdx.x & 31;
    const float4* p = (const float4*)(X + (size_t)row * 256);
    float4 u = p[lane];
    float4 w = p[lane + 32];
    float s = u.x + u.y + u.z + u.w + w.x + w.y + w.z + w.w;
    float q = u.x*u.x + u.y*u.y + u.z*u.z + u.w*u.w
            + w.x*w.x + w.y*w.y + w.z*w.z + w.w*w.w;
    #pragma unroll
    for (int o = 16; o > 0; o >>= 1) {
        s += __shfl_xor_sync(0xffffffffu, s, o);
        q += __shfl_xor_sync(0xffffffffu, q, o);
    }
    s = __shfl_sync(0xffffffffu, s, 0);
    q = __shfl_sync(0xffffffffu, q, 0);
    float m = s * (1.f / 256.f);
    float r = rsqrtf(q * (1.f / 256.f) - m * m + 1e-5f);

    float4 ga = ((const float4*)gam)[lane], gb = ((const float4*)gam)[lane + 32];
    float4 ba = ((const float4*)bet)[lane], bb = ((const float4*)bet)[lane + 32];
    int drow = WHICH ? row : dst_row(row);
    __half2* dst = (__half2*)((WHICH ? g_x2n : g_xn) + (size_t)drow * 256);
    dst[lane*2    ] = __floats2half2_rn((u.x - m)*r*ga.x + ba.x, (u.y - m)*r*ga.y + ba.y);
    dst[lane*2 + 1] = __floats2half2_rn((u.z - m)*r*ga.z + ba.z, (u.w - m)*r*ga.w + ba.w);
    dst[64 + lane*2    ] = __floats2half2_rn((w.x - m)*r*gb.x + bb.x, (w.y - m)*r*gb.y + bb.y);
    dst[64 + lane*2 + 1] = __floats2half2_rn((w.z - m)*r*gb.z + bb.z, (w.w - m)*r*gb.w + bb.w);
}

// ---------------- combined attention bias ----------------
__global__ __launch_bounds__(256)
void bias_kernel(const float* __restrict__ mask, const float* __restrict__ rpb,
                 const int* __restrict__ relidx)
{
    int wh = blockIdx.x;              // wIdx*8 + head
    int w = wh >> 3, h = wh & 7;
    for (int e = threadIdx.x; e < NTOK * NTOK; e += 256)
        g_bias[(size_t)wh * (NTOK * NTOK) + e] = mask[(size_t)w * (NTOK * NTOK) + e]
                                               + rpb[relidx[e] * NHEADS + h];
}

// ---------------- fp16 HMMA GEMM: 128x128 tile, K=32 stages, 4-deep cp.async ----------------
constexpr int E_QKV = 0, E_PROJ = 1, E_FC1 = 2, E_FC2 = 3;
#define STAGE_BYTES 10240          // 128 rows * 80B (32 halves + 16B pad)
#define SMEM_DYN    (8 * STAGE_BYTES)   // 4 stages x (A + B)

template<int EPI, int NTOT, int KTOT>
__global__ __launch_bounds__(256, 2)
void gemm_h(const float* __restrict__ x,      // PROJ: shortcut (natural order)
            const float* __restrict__ bcol,   // bias
            float* __restrict__ dout)         // FC2 output
{
    extern __shared__ char sm[];
    const __half* Ah;
    const __half* Bh;
    if (EPI == E_QKV)       { Ah = g_xn;  Bh = g_wqh;  }
    else if (EPI == E_PROJ) { Ah = g_oh;  Bh = g_wph;  }
    else if (EPI == E_FC1)  { Ah = g_x2n; Bh = g_wf1h; }
    else                    { Ah = g_h1h; Bh = g_wf2h; }

    const int tid = threadIdx.x;
    const int bn = blockIdx.x * 128;
    const int bm = blockIdx.y * 128;
    const uint32_t sb = smem_u32(sm);

    // cp.async producer role: threads 0-127 load A rows, 128-255 load B rows
    const bool isB = (tid >= 128);
    const int lrow = isB ? tid - 128 : tid;
    const __half* gsrc = isB ? (Bh + (size_t)(bn + lrow) * KTOT)
                             : (Ah + (size_t)(bm + lrow) * KTOT);
    const uint32_t dbase = sb + (isB ? 4u * STAGE_BYTES : 0u) + (uint32_t)lrow * 80u;

    constexpr int KT = KTOT / 32;
    // prologue: stages 0..2
    #pragma unroll
    for (int s = 0; s < 3; ++s) {
        const __half* g = gsrc + s * 32;
        uint32_t d = dbase + s * STAGE_BYTES;
        cp16(d, g); cp16(d + 16, g + 8); cp16(d + 32, g + 16); cp16(d + 48, g + 24);
        cp_commit();
    }

    const int warp = tid >> 5, lane = tid & 31;
    const int wm = (warp & 3) << 5;     // 4 warps over M
    const int wn = (warp >> 2) << 6;    // 2 warps over N
    const int g  = lane >> 2, tg = lane & 3;

    float acc[2][8][4];
    #pragma unroll
    for (int mi = 0; mi < 2; ++mi)
        #pragma unroll
        for (int ni = 0; ni < 8; ++ni)
            #pragma unroll
            for (int l = 0; l < 4; ++l) acc[mi][ni][l] = 0.f;

    for (int kt = 0; kt < KT; ++kt) {
        if (kt + 3 < KT) {
            const __half* gp = gsrc + (kt + 3) * 32;
            uint32_t d = dbase + ((kt + 3) & 3) * STAGE_BYTES;
            cp16(d, gp); cp16(d + 16, gp + 8); cp16(d + 32, gp + 16); cp16(d + 48, gp + 24);
        }
        cp_commit();
        cp_wait3();
        __syncthreads();

        const char* Ab = sm + (kt & 3) * STAGE_BYTES;
        const char* Bb = sm + 4 * STAGE_BYTES + (kt & 3) * STAGE_BYTES;
        #pragma unroll
        for (int kk = 0; kk < 32; kk += 16) {
            uint32_t af[2][4], bf[8][2];
            #pragma unroll
            for (int mi = 0; mi < 2; ++mi) {
                const char* r0 = Ab + (wm + mi * 16 + g) * 80 + (kk + 2 * tg) * 2;
                af[mi][0] = *(const uint32_t*)(r0);
                af[mi][1] = *(const uint32_t*)(r0 + 8 * 80);
                af[mi][2] = *(const uint32_t*)(r0 + 16);
                af[mi][3] = *(const uint32_t*)(r0 + 8 * 80 + 16);
            }
            #pragma unroll
            for (int ni = 0; ni < 8; ++ni) {
                const char* c0 = Bb + (wn + ni * 8 + g) * 80 + (kk + 2 * tg) * 2;
                bf[ni][0] = *(const uint32_t*)(c0);
                bf[ni][1] = *(const uint32_t*)(c0 + 16);
            }
            #pragma unroll
            for (int mi = 0; mi < 2; ++mi)
                #pragma unroll
                for (int ni = 0; ni < 8; ++ni)
                    hmma16(acc[mi][ni], af[mi], bf[ni]);
        }
        __syncthreads();
    }

    // ---------------- epilogue ----------------
    #pragma unroll
    for (int mi = 0; mi < 2; ++mi) {
        int r0 = bm + wm + mi * 16 + g;
        int r1 = r0 + 8;
        int s0 = 0, s1 = 0;
        if (EPI == E_PROJ) { s0 = src_row(r0); s1 = src_row(r1); }
        #pragma unroll
        for (int ni = 0; ni < 8; ++ni) {
            int col = bn + wn + ni * 8 + (tg << 1);
            float bc0 = bcol[col], bc1 = bcol[col + 1];
            float v00 = acc[mi][ni][0] + bc0;
            float v01 = acc[mi][ni][1] + bc1;
            float v10 = acc[mi][ni][2] + bc0;
            float v11 = acc[mi][ni][3] + bc1;
            if (EPI == E_QKV) {
                *(__half2*)&g_qkvh[(size_t)r0 * 768 + col] = __floats2half2_rn(v00, v01);
                *(__half2*)&g_qkvh[(size_t)r1 * 768 + col] = __floats2half2_rn(v10, v11);
            } else if (EPI == E_PROJ) {
                float2 x0 = *(const float2*)&x[(size_t)s0 * 256 + col];
                float2 x1 = *(const float2*)&x[(size_t)s1 * 256 + col];
                *(float2*)&g_x2[(size_t)s0 * 256 + col] = make_float2(x0.x + v00, x0.y + v01);
                *(float2*)&g_x2[(size_t)s1 * 256 + col] = make_float2(x1.x + v10, x1.y + v11);
            } else if (EPI == E_FC1) {
                *(__half2*)&g_h1h[(size_t)r0 * 1024 + col] = __floats2half2_rn(fgelu(v00), fgelu(v01));
                *(__half2*)&g_h1h[(size_t)r1 * 1024 + col] = __floats2half2_rn(fgelu(v10), fgelu(v11));
            } else { // E_FC2
                float2 x0 = *(const float2*)&g_x2[(size_t)r0 * 256 + col];
                float2 x1 = *(const float2*)&g_x2[(size_t)r1 * 256 + col];
                *(float2*)&dout[(size_t)r0 * 256 + col] = make_float2(x0.x + v00, x0.y + v01);
                *(float2*)&dout[(size_t)r1 * 256 + col] = make_float2(x1.x + v10, x1.y + v11);
            }
        }
    }
}

// ---------------- windowed attention (half I/O, f32 compute) ----------------
__global__ __launch_bounds__(256)
void attn_kernel()
{
    const int win  = blockIdx.x;
    const int wIdx = win & 63;
    const int tid  = threadIdx.x;
    __shared__ float qs[NTOK][33], ks[NTOK][33], vs[NTOK][33];
    __shared__ float S[NTOK][52];
    const float scale = 0.17677669529663687f;
    const __half* base = g_qkvh + (size_t)win * NTOK * 768;

    const int tn = tid >> 4, tm = tid & 15;
    int nI[4], mI[4]; bool nV[4], mV[4];
    #pragma unroll
    for (int i = 0; i < 4; ++i) {
        int n = tn + 16 * i; nV[i] = (n < NTOK); nI[i] = nV[i] ? n : 0;
        int m = tm + 16 * i; mV[i] = (m < NTOK); mI[i] = mV[i] ? m : 0;
    }
    const int lane = tid & 31;
    const int warp = tid >> 5;
    const int dpv  = tid & 31;
    const int npv  = tid >> 5;

    for (int h = 0; h < NHEADS; ++h) {
        const int hoff = h * 32;
        for (int idx = tid; idx < NTOK * 32; idx += 256) {
            int t = idx >> 5, d = idx & 31;
            const __half* rp = base + (size_t)t * 768 + hoff + d;
            qs[t][d] = __half2float(rp[0]) * scale;
            ks[t][d] = __half2float(rp[256]);
            vs[t][d] = __half2float(rp[512]);
        }
        __syncthreads();

        float acc[4][4];
        #pragma unroll
        for (int i = 0; i < 4; ++i)
            #pragma unroll
            for (int j = 0; j < 4; ++j) acc[i][j] = 0.f;
        #pragma unroll 8
        for (int d = 0; d < 32; ++d) {
            float qv[4], kv[4];
            #pragma unroll
            for (int i = 0; i < 4; ++i) qv[i] = qs[nI[i]][d];
            #pragma unroll
            for (int j = 0; j < 4; ++j) kv[j] = ks[mI[j]][d];
            #pragma unroll
            for (int i = 0; i < 4; ++i)
                #pragma unroll
                for (int j = 0; j < 4; ++j) acc[i][j] += qv[i] * kv[j];
        }
        const float* bp = g_bias + (size_t)(wIdx * NHEADS + h) * (NTOK * NTOK);
        #pragma unroll
        for (int i = 0; i < 4; ++i)
            #pragma unroll
            for (int j = 0; j < 4; ++j)
                if (nV[i] && mV[j])
                    S[nI[i]][mI[j]] = acc[i][j] + bp[nI[i] * NTOK + mI[j]];
        __syncthreads();

        for (int r = warp; r < NTOK; r += 8) {
            float v0 = S[r][lane];
            float v1 = (lane + 32 < NTOK) ? S[r][lane + 32] : -1e30f;
            float mx = fmaxf(v0, v1);
            #pragma unroll
            for (int o = 16; o > 0; o >>= 1) mx = fmaxf(mx, __shfl_xor_sync(0xffffffffu, mx, o));
            float e0 = __expf(v0 - mx);
            float e1 = (lane + 32 < NTOK) ? __expf(v1 - mx) : 0.f;
            float sm = e0 + e1;
            #pragma unroll
            for (int o = 16; o > 0; o >>= 1) sm += __shfl_xor_sync(0xffffffffu, sm, o);
            float inv = 1.f / sm;
            S[r][lane] = e0 * inv;
            if (lane + 32 < NTOK) S[r][lane + 32] = e1 * inv;
        }
        __syncthreads();

        for (int n = npv; n < NTOK; n += 8) {
            float o = 0.f;
            #pragma unroll 7
            for (int m = 0; m < NTOK; ++m) o += S[n][m] * vs[m][dpv];
            g_oh[(size_t)(win * NTOK + n) * 256 + hoff + dpv] = __float2half(o);
        }
        __syncthreads();
    }
}

// ---------------- launch ----------------
extern "C" void kernel_launch(void* const* d_in, const int* in_sizes, int n_in,
                              void* d_out, int out_size)
{
    const float* x       = (const float*)d_in[0];
    const float* norm1_g = (const float*)d_in[1];
    const float* norm1_b = (const float*)d_in[2];
    const float* qkv_w   = (const float*)d_in[3];
    const float* qkv_b   = (const float*)d_in[4];
    const float* rpb     = (const float*)d_in[5];
    const float* proj_w  = (const float*)d_in[6];
    const float* proj_b  = (const float*)d_in[7];
    const float* norm2_g = (const float*)d_in[8];
    const float* norm2_b = (const float*)d_in[9];
    const float* fc1_w   = (const float*)d_in[10];
    const float* fc1_b   = (const float*)d_in[11];
    const float* fc2_w   = (const float*)d_in[12];
    const float* fc2_b   = (const float*)d_in[13];
    const int*   relidx  = (const int*)d_in[14];
    const float* mask    = (const float*)d_in[15];
    float* out = (float*)d_out;
    (void)in_sizes; (void)n_in; (void)out_size;

    cudaFuncSetAttribute((const void*)gemm_h<E_QKV, 768, 256>,
                         cudaFuncAttributeMaxDynamicSharedMemorySize, SMEM_DYN);
    cudaFuncSetAttribute((const void*)gemm_h<E_PROJ, 256, 256>,
                         cudaFuncAttributeMaxDynamicSharedMemorySize, SMEM_DYN);
    cudaFuncSetAttribute((const void*)gemm_h<E_FC1, 1024, 256>,
                         cudaFuncAttributeMaxDynamicSharedMemorySize, SMEM_DYN);
    cudaFuncSetAttribute((const void*)gemm_h<E_FC2, 256, 1024>,
                         cudaFuncAttributeMaxDynamicSharedMemorySize, SMEM_DYN);

    w2h<<<3072, 256>>>(qkv_w, proj_w, fc1_w, fc2_w);
    bias_kernel<<<512, 256>>>(mask, rpb, relidx);
    ln_kernel<0><<<NROWS / 8, 256>>>(x, norm1_g, norm1_b);

    gemm_h<E_QKV, 768, 256><<<dim3(6, NROWS / 128), 256, SMEM_DYN>>>(x, qkv_b, nullptr);
    attn_kernel<<<NWIN, 256>>>();
    gemm_h<E_PROJ, 256, 256><<<dim3(2, NROWS / 128), 256, SMEM_DYN>>>(x, proj_b, nullptr);
    ln_kernel<1><<<NROWS / 8, 256>>>(nullptr, norm2_g, norm2_b);
    gemm_h<E_FC1, 1024, 256><<<dim3(8, NROWS / 128), 256, SMEM_DYN>>>(x, fc1_b, nullptr);
    gemm_h<E_FC2, 256, 1024><<<dim3(2, NROWS / 128), 256, SMEM_DYN>>>(x, fc2_b, out);
}

// round 14
// speedup vs baseline: 1.6762x; 1.1472x over previous
#include <cuda_runtime.h>
#include <cuda_fp16.h>
#include <cstdint>

// ---------------- problem constants ----------------
#define BB      64
#define HH      56
#define WWID    56
#define WSZ     7
#define SHIFTV  3
#define NHEADS  8
#define NTOK    49
#define NROWS   (BB*HH*WWID)     // 200704
#define NWIN    (BB*64)          // 4096 windows
#define NBIAS   (64*NHEADS*NTOK*NTOK)

// ---------------- scratch (device globals) ----------------
__device__ __half g_xn  [(size_t)NROWS * 256];   // LN1(x), window-order
__device__ __half g_qkvh[(size_t)NROWS * 768];   // qkv (window order)
__device__ __half g_oh  [(size_t)NROWS * 256];   // attention out (window order)
__device__ float  g_x2  [(size_t)NROWS * 256];   // post-attn residual (natural, f32)
__device__ __half g_x2n [(size_t)NROWS * 256];   // LN2(x2) (natural)
__device__ __half g_h1h [(size_t)NROWS * 1024];  // gelu(fc1)
__device__ float  g_bias[NBIAS];
__device__ __half g_wqh [768 * 256];
__device__ __half g_wph [256 * 256];
__device__ __half g_wf1h[1024 * 256];
__device__ __half g_wf2h[256 * 1024];

// ---------------- helpers ----------------
__device__ __forceinline__ int src_row(int r) {
    int win = r / NTOK;
    int t   = r - win * NTOK;
    int b    = win >> 6;
    int wIdx = win & 63;
    int i = t / WSZ;
    int j = t - i * WSZ;
    int hs = (wIdx >> 3) * WSZ + i;
    int ws = (wIdx & 7)  * WSZ + j;
    int h0 = hs + SHIFTV; if (h0 >= HH)   h0 -= HH;
    int w0 = ws + SHIFTV; if (w0 >= WWID) w0 -= WWID;
    return (b * HH + h0) * WWID + w0;
}
__device__ __forceinline__ int dst_row(int n) {
    int b   = n / (HH * WWID);
    int rem = n - b * (HH * WWID);
    int h0  = rem / WWID;
    int w0  = rem - h0 * WWID;
    int hs = h0 - SHIFTV; if (hs < 0) hs += HH;
    int ws = w0 - SHIFTV; if (ws < 0) ws += WWID;
    int win = b * 64 + (hs / WSZ) * 8 + (ws / WSZ);
    int tok = (hs % WSZ) * WSZ + (ws % WSZ);
    return win * NTOK + tok;
}
__device__ __forceinline__ float fgelu(float v) {
    return v / (1.f + __expf(-1.702f * v));
}
__device__ __forceinline__ uint32_t smem_u32(const void* p) {
    uint32_t a;
    asm("{ .reg .u64 t; cvta.to.shared.u64 t, %1; cvt.u32.u64 %0, t; }" : "=r"(a) : "l"(p));
    return a;
}
__device__ __forceinline__ void cp16(uint32_t dst, const void* src) {
    asm volatile("cp.async.cg.shared.global [%0], [%1], 16;" :: "r"(dst), "l"(src));
}
__device__ __forceinline__ void cp_commit() {
    asm volatile("cp.async.commit_group;");
}
__device__ __forceinline__ void cp_wait2() {
    asm volatile("cp.async.wait_group 2;");
}
__device__ __forceinline__ void hmma16(float* c, const uint32_t* a, const uint32_t* b) {
    asm volatile(
        "mma.sync.aligned.m16n8k16.row.col.f32.f16.f16.f32 "
        "{%0,%1,%2,%3},{%4,%5,%6,%7},{%8,%9},{%0,%1,%2,%3};\n"
        : "+f"(c[0]), "+f"(c[1]), "+f"(c[2]), "+f"(c[3])
        : "r"(a[0]), "r"(a[1]), "r"(a[2]), "r"(a[3]), "r"(b[0]), "r"(b[1]));
}
__device__ __forceinline__ void ldsm4(uint32_t* r, uint32_t a) {
    asm volatile("ldmatrix.sync.aligned.m8n8.x4.shared.b16 {%0,%1,%2,%3}, [%4];"
                 : "=r"(r[0]), "=r"(r[1]), "=r"(r[2]), "=r"(r[3]) : "r"(a));
}

// ---------------- weight fp16 conversion ----------------
__global__ __launch_bounds__(256)
void w2h(const float* __restrict__ qw, const float* __restrict__ pw,
         const float* __restrict__ f1, const float* __restrict__ f2)
{
    int i = blockIdx.x * 256 + threadIdx.x;      // 0 .. 786431
    if (i < 196608) g_wqh[i] = __float2half(qw[i]);
    if (i < 65536)  g_wph[i] = __float2half(pw[i]);
    if (i < 262144) { g_wf1h[i] = __float2half(f1[i]); g_wf2h[i] = __float2half(f2[i]); }
}

// ---------------- LN kernels ----------------
template<int WHICH>   // 0: LN1 x -> g_xn (permuted);  1: LN2 g_x2 -> g_x2n
__global__ __launch_bounds__(256)
void ln_kernel(const float* __restrict__ Xin,
               const float* __restrict__ gam, const float* __restrict__ bet)
{
    const float* X = WHICH ? (const float*)g_x2 : Xin;
    int row  = blockIdx.x * 8 + (threadIdx.x >> 5);
    int lane = threadIdx.x & 31;
    const float4* p = (const float4*)(X + (size_t)row * 256);
    float4 u = p[lane];
    float4 w = p[lane + 32];
    float s = u.x + u.y + u.z + u.w + w.x + w.y + w.z + w.w;
    float q = u.x*u.x + u.y*u.y + u.z*u.z + u.w*u.w
            + w.x*w.x + w.y*w.y + w.z*w.z + w.w*w.w;
    #pragma unroll
    for (int o = 16; o > 0; o >>= 1) {
        s += __shfl_xor_sync(0xffffffffu, s, o);
        q += __shfl_xor_sync(0xffffffffu, q, o);
    }
    s = __shfl_sync(0xffffffffu, s, 0);
    q = __shfl_sync(0xffffffffu, q, 0);
    float m = s * (1.f / 256.f);
    float r = rsqrtf(q * (1.f / 256.f) - m * m + 1e-5f);

    float4 ga = ((const float4*)gam)[lane], gb = ((const float4*)gam)[lane + 32];
    float4 ba = ((const float4*)bet)[lane], bb = ((const float4*)bet)[lane + 32];
    int drow = WHICH ? row : dst_row(row);
    __half2* dst = (__half2*)((WHICH ? g_x2n : g_xn) + (size_t)drow * 256);
    dst[lane*2    ] = __floats2half2_rn((u.x - m)*r*ga.x + ba.x, (u.y - m)*r*ga.y + ba.y);
    dst[lane*2 + 1] = __floats2half2_rn((u.z - m)*r*ga.z + ba.z, (u.w - m)*r*ga.w + ba.w);
    dst[64 + lane*2    ] = __floats2half2_rn((w.x - m)*r*gb.x + bb.x, (w.y - m)*r*gb.y + bb.y);
    dst[64 + lane*2 + 1] = __floats2half2_rn((w.z - m)*r*gb.z + bb.z, (w.w - m)*r*gb.w + bb.w);
}

// ---------------- combined attention bias ----------------
__global__ __launch_bounds__(256)
void bias_kernel(const float* __restrict__ mask, const float* __restrict__ rpb,
                 const int* __restrict__ relidx)
{
    int wh = blockIdx.x;              // wIdx*8 + head
    int w = wh >> 3, h = wh & 7;
    for (int e = threadIdx.x; e < NTOK * NTOK; e += 256)
        g_bias[(size_t)wh * (NTOK * NTOK) + e] = mask[(size_t)w * (NTOK * NTOK) + e]
                                               + rpb[relidx[e] * NHEADS + h];
}

// ---------------- fp16 HMMA GEMM: 128x128 tile, ldmatrix, 1 barrier/ktile ----------------
constexpr int E_QKV = 0, E_PROJ = 1, E_FC1 = 2, E_FC2 = 3;
#define STAGE_BYTES 10240          // 128 rows * 80B
#define SMEM_DYN    (8 * STAGE_BYTES)

template<int EPI, int NTOT, int KTOT>
__global__ __launch_bounds__(256, 2)
void gemm_h(const float* __restrict__ x,      // PROJ: shortcut (natural order)
            const float* __restrict__ bcol,   // bias
            float* __restrict__ dout)         // FC2 output
{
    extern __shared__ char sm[];
    const __half* Ah;
    const __half* Bh;
    if (EPI == E_QKV)       { Ah = g_xn;  Bh = g_wqh;  }
    else if (EPI == E_PROJ) { Ah = g_oh;  Bh = g_wph;  }
    else if (EPI == E_FC1)  { Ah = g_x2n; Bh = g_wf1h; }
    else                    { Ah = g_h1h; Bh = g_wf2h; }

    const int tid = threadIdx.x;
    const int bn = blockIdx.x * 128;
    const int bm = blockIdx.y * 128;
    const uint32_t sb = smem_u32(sm);

    // cp.async producers: threads 0-127 -> A rows, 128-255 -> B rows
    const bool isB = (tid >= 128);
    const int lrow = isB ? tid - 128 : tid;
    const __half* gsrc = isB ? (Bh + (size_t)(bn + lrow) * KTOT)
                             : (Ah + (size_t)(bm + lrow) * KTOT);
    const uint32_t dbase = sb + (isB ? 4u * STAGE_BYTES : 0u) + (uint32_t)lrow * 80u;

    constexpr int KT = KTOT / 32;
    #pragma unroll
    for (int s = 0; s < 3; ++s) {
        const __half* g = gsrc + s * 32;
        uint32_t d = dbase + s * STAGE_BYTES;
        cp16(d, g); cp16(d + 16, g + 8); cp16(d + 32, g + 16); cp16(d + 48, g + 24);
        cp_commit();
    }

    const int warp = tid >> 5, lane = tid & 31;
    const int wm = (warp & 3) << 5;     // 4 warps over M
    const int wn = (warp >> 2) << 6;    // 2 warps over N
    const int g  = lane >> 2, tg = lane & 3;

    // ldmatrix lane addresses (A: 2 x4 per kk covering mi; B: 4 x4 per kk covering ni pairs)
    uint32_t aaddr[2], baddr[4];
    #pragma unroll
    for (int mi = 0; mi < 2; ++mi)
        aaddr[mi] = sb + (uint32_t)(wm + mi * 16 + (lane & 15)) * 80u
                       + ((lane >> 4) & 1) * 16u;
    #pragma unroll
    for (int np = 0; np < 4; ++np)
        baddr[np] = sb + 4u * STAGE_BYTES
                       + (uint32_t)(wn + np * 16 + (lane & 7) + ((lane >> 4) & 1) * 8) * 80u
                       + ((lane >> 3) & 1) * 16u;

    float acc[2][8][4];
    #pragma unroll
    for (int mi = 0; mi < 2; ++mi)
        #pragma unroll
        for (int ni = 0; ni < 8; ++ni)
            #pragma unroll
            for (int l = 0; l < 4; ++l) acc[mi][ni][l] = 0.f;

    for (int kt = 0; kt < KT; ++kt) {
        cp_wait2();
        __syncthreads();
        const uint32_t soff = (uint32_t)(kt & 3) * STAGE_BYTES;
        #pragma unroll
        for (int kk = 0; kk < 32; kk += 16) {
            const uint32_t koff = soff + (uint32_t)kk * 2u;
            uint32_t af[2][4], bf[8][2];
            #pragma unroll
            for (int mi = 0; mi < 2; ++mi)
                ldsm4(af[mi], aaddr[mi] + koff);
            #pragma unroll
            for (int np = 0; np < 4; ++np) {
                uint32_t t4[4];
                ldsm4(t4, baddr[np] + koff);
                bf[2*np][0] = t4[0];  bf[2*np][1] = t4[1];
                bf[2*np+1][0] = t4[2]; bf[2*np+1][1] = t4[3];
            }
            #pragma unroll
            for (int mi = 0; mi < 2; ++mi)
                #pragma unroll
                for (int ni = 0; ni < 8; ++ni)
                    hmma16(acc[mi][ni], af[mi], bf[ni]);
        }
        if (kt + 3 < KT) {
            const __half* gp = gsrc + (kt + 3) * 32;
            uint32_t d = dbase + ((kt + 3) & 3) * STAGE_BYTES;
            cp16(d, gp); cp16(d + 16, gp + 8); cp16(d + 32, gp + 16); cp16(d + 48, gp + 24);
        }
        cp_commit();
    }

    // ---------------- epilogue ----------------
    #pragma unroll
    for (int mi = 0; mi < 2; ++mi) {
        int r0 = bm + wm + mi * 16 + g;
        int r1 = r0 + 8;
        int s0 = 0, s1 = 0;
        if (EPI == E_PROJ) { s0 = src_row(r0); s1 = src_row(r1); }
        #pragma unroll
        for (int ni = 0; ni < 8; ++ni) {
            int col = bn + wn + ni * 8 + (tg << 1);
            float bc0 = bcol[col], bc1 = bcol[col + 1];
            float v00 = acc[mi][ni][0] + bc0;
            float v01 = acc[mi][ni][1] + bc1;
            float v10 = acc[mi][ni][2] + bc0;
            float v11 = acc[mi][ni][3] + bc1;
            if (EPI == E_QKV) {
                *(__half2*)&g_qkvh[(size_t)r0 * 768 + col] = __floats2half2_rn(v00, v01);
                *(__half2*)&g_qkvh[(size_t)r1 * 768 + col] = __floats2half2_rn(v10, v11);
            } else if (EPI == E_PROJ) {
                float2 x0 = *(const float2*)&x[(size_t)s0 * 256 + col];
                float2 x1 = *(const float2*)&x[(size_t)s1 * 256 + col];
                *(float2*)&g_x2[(size_t)s0 * 256 + col] = make_float2(x0.x + v00, x0.y + v01);
                *(float2*)&g_x2[(size_t)s1 * 256 + col] = make_float2(x1.x + v10, x1.y + v11);
            } else if (EPI == E_FC1) {
                *(__half2*)&g_h1h[(size_t)r0 * 1024 + col] = __floats2half2_rn(fgelu(v00), fgelu(v01));
                *(__half2*)&g_h1h[(size_t)r1 * 1024 + col] = __floats2half2_rn(fgelu(v10), fgelu(v11));
            } else { // E_FC2
                float2 x0 = *(const float2*)&g_x2[(size_t)r0 * 256 + col];
                float2 x1 = *(const float2*)&g_x2[(size_t)r1 * 256 + col];
                *(float2*)&dout[(size_t)r0 * 256 + col] = make_float2(x0.x + v00, x0.y + v01);
                *(float2*)&dout[(size_t)r1 * 256 + col] = make_float2(x1.x + v10, x1.y + v11);
            }
        }
    }
}

// ---------------- windowed attention: CTA per (window, head), 128 threads ----------------
__global__ __launch_bounds__(128)
void attn_kernel()
{
    const int h    = blockIdx.x & 7;
    const int win  = blockIdx.x >> 3;
    const int wIdx = win & 63;
    const int tid  = threadIdx.x;
    __shared__ float qs[NTOK][33], ks[NTOK][33], vs[NTOK][33];
    __shared__ float S[NTOK][52];
    const float scale = 0.17677669529663687f;
    const int hoff = h * 32;
    const __half* base = g_qkvh + (size_t)win * NTOK * 768 + hoff;

    // load q (prescaled), k, v: 49 x 16 half2 each
    for (int idx = tid; idx < NTOK * 16; idx += 128) {
        int t = idx >> 4, d2 = idx & 15;
        const __half2* rp = (const __half2*)(base + (size_t)t * 768 + d2 * 2);
        float2 qv = __half22float2(rp[0]);
        float2 kv = __half22float2(rp[128]);   // +256 halves
        float2 vv = __half22float2(rp[256]);   // +512 halves
        qs[t][2*d2] = qv.x * scale; qs[t][2*d2+1] = qv.y * scale;
        ks[t][2*d2] = kv.x;         ks[t][2*d2+1] = kv.y;
        vs[t][2*d2] = vv.x;         vs[t][2*d2+1] = vv.y;
    }
    __syncthreads();

    // S = q@k^T + bias : thread grid 16(rows) x 8(cols), block 4x7
    {
        const int tn = tid >> 3, tm = tid & 7;
        int nI[4], mI[7]; bool nV[4], mV[7];
        #pragma unroll
        for (int i = 0; i < 4; ++i) {
            int n = tn + 16 * i; nV[i] = (n < NTOK); nI[i] = nV[i] ? n : 0;
        }
        #pragma unroll
        for (int j = 0; j < 7; ++j) {
            int m = tm + 8 * j; mV[j] = (m < NTOK); mI[j] = mV[j] ? m : 0;
        }
        float acc[4][7];
        #pragma unroll
        for (int i = 0; i < 4; ++i)
            #pragma unroll
            for (int j = 0; j < 7; ++j) acc[i][j] = 0.f;
        #pragma unroll 8
        for (int d = 0; d < 32; ++d) {
            float qv[4], kv[7];
            #pragma unroll
            for (int i = 0; i < 4; ++i) qv[i] = qs[nI[i]][d];
            #pragma unroll
            for (int j = 0; j < 7; ++j) kv[j] = ks[mI[j]][d];
            #pragma unroll
            for (int i = 0; i < 4; ++i)
                #pragma unroll
                for (int j = 0; j < 7; ++j) acc[i][j] += qv[i] * kv[j];
        }
        const float* bp = g_bias + (size_t)(wIdx * NHEADS + h) * (NTOK * NTOK);
        #pragma unroll
        for (int i = 0; i < 4; ++i)
            #pragma unroll
            for (int j = 0; j < 7; ++j)
                if (nV[i] && mV[j])
                    S[nI[i]][mI[j]] = acc[i][j] + bp[nI[i] * NTOK + mI[j]];
    }
    __syncthreads();

    // softmax: warp per row
    {
        const int lane = tid & 31, warp = tid >> 5;
        for (int r = warp; r < NTOK; r += 4) {
            float v0 = S[r][lane];
            float v1 = (lane + 32 < NTOK) ? S[r][lane + 32] : -1e30f;
            float mx = fmaxf(v0, v1);
            #pragma unroll
            for (int o = 16; o > 0; o >>= 1) mx = fmaxf(mx, __shfl_xor_sync(0xffffffffu, mx, o));
            float e0 = __expf(v0 - mx);
            float e1 = (lane + 32 < NTOK) ? __expf(v1 - mx) : 0.f;
            float sm = e0 + e1;
            #pragma unroll
            for (int o = 16; o > 0; o >>= 1) sm += __shfl_xor_sync(0xffffffffu, sm, o);
            float inv = 1.f / sm;
            S[r][lane] = e0 * inv;
            if (lane + 32 < NTOK) S[r][lane + 32] = e1 * inv;
        }
    }
    __syncthreads();

    // O = S @ V  (warp per row; lane = head dim)
    {
        const int d = tid & 31, warp = tid >> 5;
        for (int n = warp; n < NTOK; n += 4) {
            float o = 0.f;
            #pragma unroll 7
            for (int m = 0; m < NTOK; ++m) o += S[n][m] * vs[m][d];
            g_oh[(size_t)(win * NTOK + n) * 256 + hoff + d] = __float2half(o);
        }
    }
}

// ---------------- launch ----------------
extern "C" void kernel_launch(void* const* d_in, const int* in_sizes, int n_in,
                              void* d_out, int out_size)
{
    const float* x       = (const float*)d_in[0];
    const float* norm1_g = (const float*)d_in[1];
    const float* norm1_b = (const float*)d_in[2];
    const float* qkv_w   = (const float*)d_in[3];
    const float* qkv_b   = (const float*)d_in[4];
    const float* rpb     = (const float*)d_in[5];
    const float* proj_w  = (const float*)d_in[6];
    const float* proj_b  = (const float*)d_in[7];
    const float* norm2_g = (const float*)d_in[8];
    const float* norm2_b = (const float*)d_in[9];
    const float* fc1_w   = (const float*)d_in[10];
    const float* fc1_b   = (const float*)d_in[11];
    const float* fc2_w   = (const float*)d_in[12];
    const float* fc2_b   = (const float*)d_in[13];
    const int*   relidx  = (const int*)d_in[14];
    const float* mask    = (const float*)d_in[15];
    float* out = (float*)d_out;
    (void)in_sizes; (void)n_in; (void)out_size;

    cudaFuncSetAttribute((const void*)gemm_h<E_QKV, 768, 256>,
                         cudaFuncAttributeMaxDynamicSharedMemorySize, SMEM_DYN);
    cudaFuncSetAttribute((const void*)gemm_h<E_PROJ, 256, 256>,
                         cudaFuncAttributeMaxDynamicSharedMemorySize, SMEM_DYN);
    cudaFuncSetAttribute((const void*)gemm_h<E_FC1, 1024, 256>,
                         cudaFuncAttributeMaxDynamicSharedMemorySize, SMEM_DYN);
    cudaFuncSetAttribute((const void*)gemm_h<E_FC2, 256, 1024>,
                         cudaFuncAttributeMaxDynamicSharedMemorySize, SMEM_DYN);

    w2h<<<3072, 256>>>(qkv_w, proj_w, fc1_w, fc2_w);
    bias_kernel<<<512, 256>>>(mask, rpb, relidx);
    ln_kernel<0><<<NROWS / 8, 256>>>(x, norm1_g, norm1_b);

    gemm_h<E_QKV, 768, 256><<<dim3(6, NROWS / 128), 256, SMEM_DYN>>>(x, qkv_b, nullptr);
    attn_kernel<<<NWIN * NHEADS, 128>>>();
    gemm_h<E_PROJ, 256, 256><<<dim3(2, NROWS / 128), 256, SMEM_DYN>>>(x, proj_b, nullptr);
    ln_kernel<1><<<NROWS / 8, 256>>>(nullptr, norm2_g, norm2_b);
    gemm_h<E_FC1, 1024, 256><<<dim3(8, NROWS / 128), 256, SMEM_DYN>>>(x, fc1_b, nullptr);
    gemm_h<E_FC2, 256, 1024><<<dim3(2, NROWS / 128), 256, SMEM_DYN>>>(x, fc2_b, out);
}